// round 4
// baseline (speedup 1.0000x reference)
#include <cuda_runtime.h>
#include <cstdint>
#include <cstddef>

// Problem constants (fixed shapes for this dataset)
#define NN     4096     // N*N
#define CC     256      // feature dim
#define BB     32       // batch (videos)
#define SS     64       // sentences
#define PT2    256      // proposals per block tile
#define KC     32       // K-chunk staged in smem
#define TPB2   256      // threads in score kernel
#define MAXT   (NN/PT2) // worst-case tiles (16)

#define INV_T 10.0f     // 1 / 0.1
#define EPSN  1e-12f

// ---------------- device scratch (no allocations allowed) ----------------
__device__ int   g_flat[NN];            // compacted proposal -> flat (i*N+j)
__device__ int   g_P;                   // number of valid proposals
__device__ int   g_scatter[SS];         // sentence -> video index
__device__ float g_sf[SS*CC];           // normalized sentence feats [s][c]
__device__ unsigned long long g_sfD[CC*SS]; // duplicated pairs [c][s] = {v,v}
__device__ float g_partial[BB*MAXT*SS]; // per-block partial neg-exp sums
__device__ float g_negsum[SS];          // inter-query neg sums
__device__ int   g_pstar[SS];           // per-sentence argmax proposal
__device__ float g_A[SS*SS];            // A[s][t] = dot(topk_video[s], sf[t])

// packed fp32x2 helpers (SASS FFMA2 — only reachable via PTX)
__device__ __forceinline__ void ffma2(unsigned long long& acc,
                                      unsigned long long w,
                                      unsigned long long v) {
    asm("fma.rn.f32x2 %0, %1, %2, %0;" : "+l"(acc) : "l"(w), "l"(v));
}
__device__ __forceinline__ unsigned long long pack2(float x) {
    unsigned long long r;
    asm("mov.b64 %0, {%1, %1};" : "=l"(r) : "r"(__float_as_uint(x)));
    return r;
}
__device__ __forceinline__ float unpack_lo(unsigned long long u) {
    return __uint_as_float((unsigned)(u & 0xffffffffu));
}
__device__ __forceinline__ float unpack_hi(unsigned long long u) {
    return __uint_as_float((unsigned)(u >> 32));
}

// ---------------- setup: compact mask + scatter indices ----------------
__global__ void setup_kernel(const unsigned char* __restrict__ mask,
                             const int* __restrict__ num_targets) {
    __shared__ int wsum[32];
    __shared__ int mode_s;
    int t = threadIdx.x;                  // 1024 threads, 4 entries each
    if (t == 0) mode_s = (mask[1] != 0);  // byte-bool vs 4-byte encoding
    __syncthreads();
    int mode = mode_s;

    int pred[4], cnt = 0;
#pragma unroll
    for (int k = 0; k < 4; k++) {
        int idx = t * 4 + k;
        int m = mode ? (mask[idx] != 0)
                     : (((const int*)mask)[idx] != 0);
        pred[k] = m; cnt += m;
    }
    int lane = t & 31, w = t >> 5;
    int inc = cnt;
#pragma unroll
    for (int off = 1; off < 32; off <<= 1) {
        int y = __shfl_up_sync(0xffffffffu, inc, off);
        if (lane >= off) inc += y;
    }
    if (lane == 31) wsum[w] = inc;
    __syncthreads();
    if (w == 0) {
        int v = wsum[lane];
#pragma unroll
        for (int off = 1; off < 32; off <<= 1) {
            int y = __shfl_up_sync(0xffffffffu, v, off);
            if (lane >= off) v += y;
        }
        wsum[lane] = v;
    }
    __syncthreads();
    int base = (w ? wsum[w - 1] : 0) + inc - cnt;
#pragma unroll
    for (int k = 0; k < 4; k++) {
        if (pred[k]) g_flat[base++] = t * 4 + k;
    }
    if (t == blockDim.x - 1) g_P = wsum[31];

    if (t == 0) {
        int off = 0;
        for (int b = 0; b < BB && off < SS; b++) {
            int n = num_targets[b];
            for (int k = 0; k < n && off < SS; k++) g_scatter[off++] = b;
        }
    }
}

// ---------------- normalize sentence features ----------------
__global__ void norm_sents(const float* __restrict__ sents) {
    int s = blockIdx.x, c = threadIdx.x;   // SS blocks x CC threads
    __shared__ float sm[CC];
    float x = sents[s * CC + c];
    sm[c] = x * x;
    __syncthreads();
    for (int st = CC / 2; st > 0; st >>= 1) {
        if (c < st) sm[c] += sm[c + st];
        __syncthreads();
    }
    float inv = 1.0f / fmaxf(sqrtf(sm[0]), EPSN);
    float v = x * inv;
    g_sf[s * CC + c]   = v;
    g_sfD[c * SS + s]  = pack2(v);
}

// ---------------- per-sentence argmax over gathered iou ----------------
__global__ void argmax_k(const float* __restrict__ iou) {
    int s = blockIdx.x, t = threadIdx.x;   // SS blocks x 256 threads
    int P = g_P;
    __shared__ float bv[256];
    __shared__ int   bi[256];
    float best = -1e30f;
    int bp = 1 << 30;
    for (int p = t; p < P; p += 256) {
        float v = iou[s * NN + g_flat[p]];
        if (v > best) { best = v; bp = p; }   // ascending p => first max kept
    }
    bv[t] = best; bi[t] = bp;
    __syncthreads();
    for (int st = 128; st > 0; st >>= 1) {
        if (t < st) {
            if (bv[t + st] > bv[t] || (bv[t + st] == bv[t] && bi[t + st] < bi[t])) {
                bv[t] = bv[t + st]; bi[t] = bi[t + st];
            }
        }
        __syncthreads();
    }
    if (t == 0) g_pstar[s] = g_flat[bi[0]];
}

// ---------------- main fused score kernel: register-tiled GEMM ----------
// Block tile: 256 proposals x 64 sentences, K chunked by 32 through smem.
// 256 threads; lane tp=tid&31 owns 8 contiguous proposals, warp ts=tid>>5
// owns 8 sentences. Per k per thread: 2 LDS.128 (dense contiguous) +
// 4 LDS.128 (pure broadcast) + 36 FFMA2 (incl. fused ssq). Per-sentence
// reductions stay within one warp (shuffles, deterministic order).
__global__ __launch_bounds__(TPB2, 2)
void score_kernel(const float* __restrict__ video,
                  const float* __restrict__ iou) {
    const int P = g_P;
    const int tile = blockIdx.x;
    const int tbase = tile * PT2;
    if (tbase >= P) return;                // dead padding tile
    const int b = blockIdx.y;

    extern __shared__ float smem_dyn[];
    float* vt = smem_dyn;                                   // [KC][PT2] 32KB
    unsigned long long* sfd =
        (unsigned long long*)(smem_dyn + KC * PT2);         // [KC][SS] 16KB
    __shared__ int scat[SS];
    __shared__ int gflat_s[PT2];

    const int tid = threadIdx.x;
    if (tid < SS) scat[tid] = g_scatter[tid];
    gflat_s[tid] = (tbase + tid < P) ? g_flat[tbase + tid] : -1;

    const int tp = tid & 31;        // lane: 8 contiguous proposals tp*8..
    const int ts = tid >> 5;        // warp: 8 sentences ts*8..
    const size_t vbase = (size_t)b * CC * NN;

    unsigned long long acc[4][8];   // [ppair][s]
#pragma unroll
    for (int j = 0; j < 4; j++)
#pragma unroll
        for (int i = 0; i < 8; i++) acc[j][i] = 0ull;
    unsigned long long ssq2[4];
#pragma unroll
    for (int j = 0; j < 4; j++) ssq2[j] = 0ull;

    __syncthreads();                // gflat_s ready
    const int gme = gflat_s[tid];   // staging proposal for this thread

    for (int ch = 0; ch < CC / KC; ch++) {
        const int c0 = ch * KC;
        // stage video tile: thread tid owns proposal column tid, all k
        if (gme >= 0) {
#pragma unroll 8
            for (int c = 0; c < KC; c++)
                vt[c * PT2 + tid] = __ldg(&video[vbase + (size_t)(c0 + c) * NN + gme]);
        } else {
#pragma unroll 8
            for (int c = 0; c < KC; c++) vt[c * PT2 + tid] = 0.0f;
        }
        // stage duplicated sentence pairs: 2048 u64 / 256 threads, vec2
        {
            const ulonglong2* src = (const ulonglong2*)&g_sfD[c0 * SS];
            ulonglong2* dst = (ulonglong2*)sfd;
#pragma unroll
            for (int i = 0; i < (KC * SS / 2) / TPB2; i++)   // 4
                dst[tid + i * TPB2] = src[tid + i * TPB2];
        }
        __syncthreads();

#pragma unroll 4
        for (int k = 0; k < KC; k++) {
            const float* vrow = vt + k * PT2 + tp * 8;
            ulonglong2 va0 = *reinterpret_cast<const ulonglong2*>(vrow);
            ulonglong2 va1 = *reinterpret_cast<const ulonglong2*>(vrow + 4);
            const unsigned long long* srow = sfd + k * SS + ts * 8;
            ulonglong2 s0 = *reinterpret_cast<const ulonglong2*>(srow);
            ulonglong2 s1 = *reinterpret_cast<const ulonglong2*>(srow + 2);
            ulonglong2 s2 = *reinterpret_cast<const ulonglong2*>(srow + 4);
            ulonglong2 s3 = *reinterpret_cast<const ulonglong2*>(srow + 6);

            ffma2(ssq2[0], va0.x, va0.x);
            ffma2(ssq2[1], va0.y, va0.y);
            ffma2(ssq2[2], va1.x, va1.x);
            ffma2(ssq2[3], va1.y, va1.y);
#pragma unroll
            for (int j = 0; j < 4; j++) {
                unsigned long long vv = j == 0 ? va0.x : j == 1 ? va0.y
                                      : j == 2 ? va1.x : va1.y;
                ffma2(acc[j][0], s0.x, vv);
                ffma2(acc[j][1], s0.y, vv);
                ffma2(acc[j][2], s1.x, vv);
                ffma2(acc[j][3], s1.y, vv);
                ffma2(acc[j][4], s2.x, vv);
                ffma2(acc[j][5], s2.y, vv);
                ffma2(acc[j][6], s3.x, vv);
                ffma2(acc[j][7], s3.y, vv);
            }
        }
        __syncthreads();
    }

    // per-proposal 1/norm * (1/t), from fused ssq accumulators
    float inv[8];
    int   gg[8];
#pragma unroll
    for (int j = 0; j < 4; j++) {
        inv[2 * j]     = rsqrtf(fmaxf(unpack_lo(ssq2[j]), 1e-24f)) * INV_T;
        inv[2 * j + 1] = rsqrtf(fmaxf(unpack_hi(ssq2[j]), 1e-24f)) * INV_T;
    }
#pragma unroll
    for (int jj = 0; jj < 8; jj++) gg[jj] = gflat_s[tp * 8 + jj];

    const int lane = tp;
    const size_t pbase = ((size_t)b * MAXT + tile) * SS;
#pragma unroll 1
    for (int i = 0; i < 8; i++) {
        int s = ts * 8 + i;
        bool same = (scat[s] == b);
        float esum = 0.0f;
#pragma unroll
        for (int j = 0; j < 4; j++) {
            int g0 = gg[2 * j], g1 = gg[2 * j + 1];
            if (g0 >= 0) {
                bool pos = same && (iou[s * NN + g0] > 0.5f);
                if (!pos) esum += __expf(unpack_lo(acc[j][i]) * inv[2 * j]);
            }
            if (g1 >= 0) {
                bool pos = same && (iou[s * NN + g1] > 0.5f);
                if (!pos) esum += __expf(unpack_hi(acc[j][i]) * inv[2 * j + 1]);
            }
        }
#pragma unroll
        for (int off = 16; off; off >>= 1)
            esum += __shfl_down_sync(0xffffffffu, esum, off);
        if (lane == 0) g_partial[pbase + s] = esum;
    }
}

// ---------------- deterministic reduction of partials ----------------
__global__ void reduce_neg() {
    int s = blockIdx.x;            // SS blocks x 256 threads
    int t = threadIdx.x;
    int used = (g_P + PT2 - 1) / PT2;   // live tiles per video
    __shared__ float sm[256];
    float sum = 0.0f;
    for (int i = t; i < BB * MAXT; i += 256) {
        int tl = i % MAXT;
        if (tl < used) sum += g_partial[i * SS + s];
    }
    sm[t] = sum;
    __syncthreads();
    for (int st = 128; st > 0; st >>= 1) {
        if (t < st) sm[t] += sm[t + st];
        __syncthreads();
    }
    if (t == 0) g_negsum[s] = sm[0];
}

// ---------------- A[s][t] = dot(normalized topk proposal of s, sf[t]) ----
__global__ void topk_dots(const float* __restrict__ video) {
    int s = blockIdx.x, t = threadIdx.x;   // SS blocks x 256 threads
    __shared__ float tv[CC];
    __shared__ float rs[CC];
    int b = g_scatter[s];
    int g = g_pstar[s];
    float v = video[((size_t)(b * CC + t)) * NN + g];
    rs[t] = v * v;
    __syncthreads();
    for (int st = 128; st > 0; st >>= 1) {
        if (t < st) rs[t] += rs[t + st];
        __syncthreads();
    }
    float inv = 1.0f / fmaxf(sqrtf(rs[0]), EPSN);
    tv[t] = v * inv;
    __syncthreads();
    int lane = t & 31, wrp = t >> 5;
    for (int q = wrp; q < SS; q += 8) {
        float d = 0.0f;
        for (int c = lane; c < CC; c += 32) d += g_sf[q * CC + c] * tv[c];
#pragma unroll
        for (int off = 16; off; off >>= 1)
            d += __shfl_down_sync(0xffffffffu, d, off);
        if (lane == 0) g_A[s * SS + q] = d;
    }
}

// ---------------- final losses ----------------
__global__ void finalize(float* __restrict__ out) {
    __shared__ float l1[SS], l2[SS];
    int s = threadIdx.x;   // SS threads
    float pos = g_A[s * SS + s];
    float nsv = 0.0f;
    for (int u = 0; u < SS; u++)
        if (u != s) nsv += expf(g_A[s * SS + u] * INV_T);
    float pe = expf(pos * INV_T);
    float lv = -(pos * INV_T - logf(pe + nsv));
    float lq = -(pos * INV_T - logf(pe + g_negsum[s]));
    l1[s] = lv; l2[s] = lq;
    __syncthreads();
    for (int st = 32; st > 0; st >>= 1) {
        if (s < st) { l1[s] += l1[s + st]; l2[s] += l2[s + st]; }
        __syncthreads();
    }
    if (s == 0) {
        out[0] = l1[0] / (float)SS;  // loss_inter_video
        out[1] = l2[0] / (float)SS;  // loss_inter_query
    }
}

// ---------------- launcher ----------------
extern "C" void kernel_launch(void* const* d_in, const int* in_sizes, int n_in,
                              void* d_out, int out_size) {
    const float*         video = (const float*)d_in[0];         // [B,C,N,N]
    const float*         sents = (const float*)d_in[1];         // [S,C]
    const int*           ntgt  = (const int*)d_in[2];           // [B]
    const float*         iou   = (const float*)d_in[3];         // [S,N,N]
    const unsigned char* mask  = (const unsigned char*)d_in[4]; // [N,N] bool
    float* out = (float*)d_out;

    const int smem_bytes = (KC * PT2) * 4 + (KC * SS) * 8;      // 48 KB
    cudaFuncSetAttribute(score_kernel,
                         cudaFuncAttributeMaxDynamicSharedMemorySize, smem_bytes);

    setup_kernel<<<1, 1024>>>(mask, ntgt);
    norm_sents<<<SS, CC>>>(sents);
    argmax_k<<<SS, 256>>>(iou);
    dim3 grid(MAXT, BB);
    score_kernel<<<grid, TPB2, smem_bytes>>>(video, iou);
    reduce_neg<<<SS, 256>>>();
    topk_dots<<<SS, 256>>>(video);
    finalize<<<1, SS>>>(out);
}

// round 5
// speedup vs baseline: 1.4695x; 1.4695x over previous
#include <cuda_runtime.h>
#include <cstdint>
#include <cstddef>

// Problem constants (fixed shapes for this dataset)
#define NN     4096     // N*N
#define CC     256      // feature dim
#define BB     32       // batch (videos)
#define SS     64       // sentences
#define PT     128      // proposals per block tile
#define KC     32       // K-chunk staged in smem
#define TPB2   256      // threads in score kernel
#define MAXT   (NN/PT)  // worst-case tiles (32)
#define CHN    (CC/KC)  // 8 chunks

#define INV_T 10.0f     // 1 / 0.1
#define EPSN  1e-12f

// ---------------- device scratch (no allocations allowed) ----------------
__device__ int   g_flat[NN];            // compacted proposal -> flat (i*N+j)
__device__ int   g_P;                   // number of valid proposals
__device__ int   g_scatter[SS];         // sentence -> video index
__device__ float g_sf[SS*CC];           // normalized sentence feats [s][c]
__device__ __align__(16) unsigned long long g_sfD[CC*SS]; // dup pairs [c][s]
__device__ float g_partial[BB*MAXT*SS]; // per-block partial neg-exp sums
__device__ float g_negsum[SS];          // inter-query neg sums
__device__ int   g_pstar[SS];           // per-sentence argmax proposal
__device__ float g_A[SS*SS];            // A[s][t] = dot(topk_video[s], sf[t])

// packed fp32x2 helpers (SASS FFMA2 — only reachable via PTX)
__device__ __forceinline__ void ffma2(unsigned long long& acc,
                                      unsigned long long w,
                                      unsigned long long v) {
    asm("fma.rn.f32x2 %0, %1, %2, %0;" : "+l"(acc) : "l"(w), "l"(v));
}
__device__ __forceinline__ unsigned long long pack2(float x) {
    unsigned long long r;
    asm("mov.b64 %0, {%1, %1};" : "=l"(r) : "r"(__float_as_uint(x)));
    return r;
}
__device__ __forceinline__ float unpack_lo(unsigned long long u) {
    return __uint_as_float((unsigned)(u & 0xffffffffu));
}
__device__ __forceinline__ float unpack_hi(unsigned long long u) {
    return __uint_as_float((unsigned)(u >> 32));
}
__device__ __forceinline__ void cp_async4(uint32_t saddr, const void* gptr) {
    asm volatile("cp.async.ca.shared.global [%0], [%1], 4;"
                 :: "r"(saddr), "l"(gptr) : "memory");
}
__device__ __forceinline__ void cp_async16(uint32_t saddr, const void* gptr) {
    asm volatile("cp.async.cg.shared.global [%0], [%1], 16;"
                 :: "r"(saddr), "l"(gptr) : "memory");
}

// ---------------- setup: compact mask + scatter indices ----------------
__global__ void setup_kernel(const unsigned char* __restrict__ mask,
                             const int* __restrict__ num_targets) {
    __shared__ int wsum[32];
    __shared__ int mode_s;
    int t = threadIdx.x;                  // 1024 threads, 4 entries each
    if (t == 0) mode_s = (mask[1] != 0);  // byte-bool vs 4-byte encoding
    __syncthreads();
    int mode = mode_s;

    int pred[4], cnt = 0;
#pragma unroll
    for (int k = 0; k < 4; k++) {
        int idx = t * 4 + k;
        int m = mode ? (mask[idx] != 0)
                     : (((const int*)mask)[idx] != 0);
        pred[k] = m; cnt += m;
    }
    int lane = t & 31, w = t >> 5;
    int inc = cnt;
#pragma unroll
    for (int off = 1; off < 32; off <<= 1) {
        int y = __shfl_up_sync(0xffffffffu, inc, off);
        if (lane >= off) inc += y;
    }
    if (lane == 31) wsum[w] = inc;
    __syncthreads();
    if (w == 0) {
        int v = wsum[lane];
#pragma unroll
        for (int off = 1; off < 32; off <<= 1) {
            int y = __shfl_up_sync(0xffffffffu, v, off);
            if (lane >= off) v += y;
        }
        wsum[lane] = v;
    }
    __syncthreads();
    int base = (w ? wsum[w - 1] : 0) + inc - cnt;
#pragma unroll
    for (int k = 0; k < 4; k++) {
        if (pred[k]) g_flat[base++] = t * 4 + k;
    }
    if (t == blockDim.x - 1) g_P = wsum[31];

    if (t == 0) {
        int off = 0;
        for (int b = 0; b < BB && off < SS; b++) {
            int n = num_targets[b];
            for (int k = 0; k < n && off < SS; k++) g_scatter[off++] = b;
        }
    }
}

// ---------------- prep: normalize sentences + per-sentence iou argmax ----
__global__ void prep_kernel(const float* __restrict__ sents,
                            const float* __restrict__ iou) {
    int s = blockIdx.x, t = threadIdx.x;   // SS blocks x 256 threads
    __shared__ float sm[256];
    float x = sents[s * CC + t];
    sm[t] = x * x;
    __syncthreads();
    for (int st = 128; st > 0; st >>= 1) {
        if (t < st) sm[t] += sm[t + st];
        __syncthreads();
    }
    float inv = 1.0f / fmaxf(sqrtf(sm[0]), EPSN);
    float v = x * inv;
    g_sf[s * CC + t]  = v;
    g_sfD[t * SS + s] = pack2(v);

    // argmax over gathered iou (first-max-kept semantics)
    int P = g_P;
    __shared__ float bv[256];
    __shared__ int   bi[256];
    float best = -1e30f;
    int bp = 1 << 30;
    for (int p = t; p < P; p += 256) {
        float vv = iou[s * NN + g_flat[p]];
        if (vv > best) { best = vv; bp = p; }
    }
    bv[t] = best; bi[t] = bp;
    __syncthreads();
    for (int st = 128; st > 0; st >>= 1) {
        if (t < st) {
            if (bv[t + st] > bv[t] || (bv[t + st] == bv[t] && bi[t + st] < bi[t])) {
                bv[t] = bv[t + st]; bi[t] = bi[t + st];
            }
        }
        __syncthreads();
    }
    if (t == 0) g_pstar[s] = g_flat[bi[0]];
}

// ---------------- main fused score kernel ----------------
// Register-tiled GEMM (128p x 64s tile, K chunked by 32) with a cp.async
// double-buffered pipeline. Thread (tp=tid&15, ts=tid>>4) owns 8 proposals
// as two contiguous quads (tp*4 and 64+tp*4 -> conflict-free LDS.128) and
// 4 sentences. Inner loop per k: 2 LDS.128 (dense) + 2 LDS.128 (broadcast)
// + 20 FFMA2 (16 acc + 4 fused ssq). acc = 16 u64 keeps the allocation in
// the conflict-free FFMA2 regime (R3) while cp.async hides staging.
__global__ __launch_bounds__(TPB2, 3)
void score_kernel(const float* __restrict__ video,
                  const float* __restrict__ iou) {
    const int P = g_P;
    const int tile = blockIdx.x;
    const int tbase = tile * PT;
    if (tbase >= P) return;                // dead padding tile
    const int b = blockIdx.y;

    extern __shared__ float smem[];
    float* vtb0 = smem;                    // [KC][PT]
    float* vtb1 = smem + KC * PT;
    unsigned long long* sfb0 = (unsigned long long*)(smem + 2 * KC * PT);
    unsigned long long* sfb1 = sfb0 + KC * SS;
    __shared__ int scat[SS];
    __shared__ int gflat_s[PT];

    const int tid = threadIdx.x;
    if (tid < SS) scat[tid] = g_scatter[tid];
    if (tid < PT) gflat_s[tid] = (tbase + tid < P) ? g_flat[tbase + tid] : -1;
    __syncthreads();

    const int pcol = tid & (PT - 1);
    const int crow = tid >> 7;             // 0 or 1
    const int gme  = gflat_s[pcol];
    const size_t vbase = (size_t)b * CC * NN;

    uint32_t vt_s0 = (uint32_t)__cvta_generic_to_shared(vtb0);
    uint32_t vt_s1 = (uint32_t)__cvta_generic_to_shared(vtb1);
    uint32_t sf_s0 = (uint32_t)__cvta_generic_to_shared(sfb0);
    uint32_t sf_s1 = (uint32_t)__cvta_generic_to_shared(sfb1);

    auto stage = [&](int ch, int bsel) {
        const int c0 = ch * KC;
        float* vtb = bsel ? vtb1 : vtb0;
        uint32_t vts = (bsel ? vt_s1 : vt_s0) + (uint32_t)((crow * PT + pcol) * 4);
        if (gme >= 0) {
            const float* gp = video + vbase + (size_t)(c0 + crow) * NN + gme;
#pragma unroll
            for (int i = 0; i < KC / 2; i++)         // 16 rows per thread-half
                cp_async4(vts + (uint32_t)(i * 2 * PT * 4), gp + (size_t)(2 * i) * NN);
        } else {
#pragma unroll
            for (int i = 0; i < KC / 2; i++)
                vtb[(crow + 2 * i) * PT + pcol] = 0.0f;
        }
        const char* sg = (const char*)(g_sfD + (size_t)c0 * SS) + (size_t)tid * 16;
        uint32_t sfs = (bsel ? sf_s1 : sf_s0) + (uint32_t)(tid * 16);
#pragma unroll
        for (int j = 0; j < 4; j++)                  // 1024 x 16B total
            cp_async16(sfs + (uint32_t)(j * TPB2 * 16), sg + (size_t)j * TPB2 * 16);
    };

    const int tp = tid & 15;        // proposal group
    const int ts = tid >> 4;        // sentence group: 4 sentences ts*4..
    unsigned long long acc[4][4];   // [ppair][s]
#pragma unroll
    for (int j = 0; j < 4; j++)
#pragma unroll
        for (int i = 0; i < 4; i++) acc[j][i] = 0ull;
    unsigned long long ssq2[4];
#pragma unroll
    for (int j = 0; j < 4; j++) ssq2[j] = 0ull;

    stage(0, 0);
    asm volatile("cp.async.commit_group;" ::: "memory");

#pragma unroll 1
    for (int ch = 0; ch < CHN; ch++) {
        const int cur = ch & 1;
        if (ch + 1 < CHN) {
            stage(ch + 1, cur ^ 1);
            asm volatile("cp.async.commit_group;" ::: "memory");
            asm volatile("cp.async.wait_group 1;" ::: "memory");
        } else {
            asm volatile("cp.async.wait_group 0;" ::: "memory");
        }
        __syncthreads();

        const float* vt = cur ? vtb1 : vtb0;
        const unsigned long long* sfd = cur ? sfb1 : sfb0;
#pragma unroll 4
        for (int k = 0; k < KC; k++) {
            const float* vrow = vt + k * PT;
            ulonglong2 va0 = *reinterpret_cast<const ulonglong2*>(vrow + tp * 4);
            ulonglong2 va1 = *reinterpret_cast<const ulonglong2*>(vrow + 64 + tp * 4);
            const unsigned long long* srow = sfd + k * SS + ts * 4;
            ulonglong2 s0 = *reinterpret_cast<const ulonglong2*>(srow);
            ulonglong2 s1 = *reinterpret_cast<const ulonglong2*>(srow + 2);

            ffma2(ssq2[0], va0.x, va0.x);
            ffma2(ssq2[1], va0.y, va0.y);
            ffma2(ssq2[2], va1.x, va1.x);
            ffma2(ssq2[3], va1.y, va1.y);
#pragma unroll
            for (int j = 0; j < 4; j++) {
                unsigned long long vv = j == 0 ? va0.x : j == 1 ? va0.y
                                      : j == 2 ? va1.x : va1.y;
                ffma2(acc[j][0], s0.x, vv);
                ffma2(acc[j][1], s0.y, vv);
                ffma2(acc[j][2], s1.x, vv);
                ffma2(acc[j][3], s1.y, vv);
            }
        }
        __syncthreads();
    }

    // per-proposal 1/norm * (1/t) from fused ssq; pair j -> proposals:
    //   j<2:  p = tp*4 + 2j, +1        j>=2: p = 64 + tp*4 + 2(j-2), +1
    float inv[8];
    int   gg[8];
#pragma unroll
    for (int j = 0; j < 4; j++) {
        int pj = (j < 2) ? (tp * 4 + 2 * j) : (64 + tp * 4 + 2 * (j - 2));
        inv[2 * j]     = rsqrtf(fmaxf(unpack_lo(ssq2[j]), 1e-24f)) * INV_T;
        inv[2 * j + 1] = rsqrtf(fmaxf(unpack_hi(ssq2[j]), 1e-24f)) * INV_T;
        gg[2 * j]      = gflat_s[pj];
        gg[2 * j + 1]  = gflat_s[pj + 1];
    }

    const size_t pbase = ((size_t)b * MAXT + tile) * SS;
#pragma unroll 1
    for (int i = 0; i < 4; i++) {
        int s = ts * 4 + i;
        bool same = (scat[s] == b);
        float esum = 0.0f;
#pragma unroll
        for (int j = 0; j < 4; j++) {
            int g0 = gg[2 * j], g1 = gg[2 * j + 1];
            if (g0 >= 0) {
                bool pos = same && (iou[s * NN + g0] > 0.5f);
                if (!pos) esum += __expf(unpack_lo(acc[j][i]) * inv[2 * j]);
            }
            if (g1 >= 0) {
                bool pos = same && (iou[s * NN + g1] > 0.5f);
                if (!pos) esum += __expf(unpack_hi(acc[j][i]) * inv[2 * j + 1]);
            }
        }
        // reduce across the 16 proposal-groups (width-16 shuffle segments)
#pragma unroll
        for (int off = 8; off; off >>= 1)
            esum += __shfl_down_sync(0xffffffffu, esum, off, 16);
        if (tp == 0) g_partial[pbase + s] = esum;
    }
}

// ---------------- tail: reduce partials + topk dots (fused) ----------------
__global__ void tail_kernel(const float* __restrict__ video) {
    int s = blockIdx.x, t = threadIdx.x;   // SS blocks x 256 threads

    // part 1: deterministic reduction of inter-query partials
    {
        int used = (g_P + PT - 1) / PT;    // live tiles per video
        __shared__ float sm[256];
        float sum = 0.0f;
        for (int i = t; i < BB * MAXT; i += 256) {
            int tl = i % MAXT;
            if (tl < used) sum += g_partial[i * SS + s];
        }
        sm[t] = sum;
        __syncthreads();
        for (int st = 128; st > 0; st >>= 1) {
            if (t < st) sm[t] += sm[t + st];
            __syncthreads();
        }
        if (t == 0) g_negsum[s] = sm[0];
        __syncthreads();
    }

    // part 2: A[s][t] = dot(normalized topk proposal of s, sf[t])
    {
        __shared__ float tv[CC];
        __shared__ float rs[CC];
        int b = g_scatter[s];
        int g = g_pstar[s];
        float v = video[((size_t)(b * CC + t)) * NN + g];
        rs[t] = v * v;
        __syncthreads();
        for (int st = 128; st > 0; st >>= 1) {
            if (t < st) rs[t] += rs[t + st];
            __syncthreads();
        }
        float inv = 1.0f / fmaxf(sqrtf(rs[0]), EPSN);
        tv[t] = v * inv;
        __syncthreads();
        int lane = t & 31, wrp = t >> 5;
        for (int q = wrp; q < SS; q += 8) {
            float d = 0.0f;
            for (int c = lane; c < CC; c += 32) d += g_sf[q * CC + c] * tv[c];
#pragma unroll
            for (int off = 16; off; off >>= 1)
                d += __shfl_down_sync(0xffffffffu, d, off);
            if (lane == 0) g_A[s * SS + q] = d;
        }
    }
}

// ---------------- final losses ----------------
__global__ void finalize(float* __restrict__ out) {
    __shared__ float l1[SS], l2[SS];
    int s = threadIdx.x;   // SS threads
    float pos = g_A[s * SS + s];
    float nsv = 0.0f;
    for (int u = 0; u < SS; u++)
        if (u != s) nsv += expf(g_A[s * SS + u] * INV_T);
    float pe = expf(pos * INV_T);
    float lv = -(pos * INV_T - logf(pe + nsv));
    float lq = -(pos * INV_T - logf(pe + g_negsum[s]));
    l1[s] = lv; l2[s] = lq;
    __syncthreads();
    for (int st = 32; st > 0; st >>= 1) {
        if (s < st) { l1[s] += l1[s + st]; l2[s] += l2[s + st]; }
        __syncthreads();
    }
    if (s == 0) {
        out[0] = l1[0] / (float)SS;  // loss_inter_video
        out[1] = l2[0] / (float)SS;  // loss_inter_query
    }
}

// ---------------- launcher ----------------
extern "C" void kernel_launch(void* const* d_in, const int* in_sizes, int n_in,
                              void* d_out, int out_size) {
    const float*         video = (const float*)d_in[0];         // [B,C,N,N]
    const float*         sents = (const float*)d_in[1];         // [S,C]
    const int*           ntgt  = (const int*)d_in[2];           // [B]
    const float*         iou   = (const float*)d_in[3];         // [S,N,N]
    const unsigned char* mask  = (const unsigned char*)d_in[4]; // [N,N] bool
    float* out = (float*)d_out;

    const int smem_bytes = 2 * KC * PT * 4 + 2 * KC * SS * 8;   // 64 KB
    cudaFuncSetAttribute(score_kernel,
                         cudaFuncAttributeMaxDynamicSharedMemorySize, smem_bytes);

    setup_kernel<<<1, 1024>>>(mask, ntgt);
    prep_kernel<<<SS, 256>>>(sents, iou);
    dim3 grid(MAXT, BB);
    score_kernel<<<grid, TPB2, smem_bytes>>>(video, iou);
    tail_kernel<<<SS, 256>>>(video);
    finalize<<<1, SS>>>(out);
}